// round 9
// baseline (speedup 1.0000x reference)
#include <cuda_runtime.h>
#include <cuda_bf16.h>
#include <cstdint>

// KernelApply: out[b,c,h,w] = sum_{i,j} softmax(kern[b,:,h,w])[i*5+j] * data_pad[b,c,h+i-2,w+j-2]
// data: [B,C,H,W] f32; kernels: [B,25,H,W] f32; out: [B,C,H,W] f32
//
// v9 = v8 compute mix (2 px/thread, taps in smem via TMA, data via LDG.64)
//    + v7 pipeline (8 tiles per CTA, 2-buffer tap ring -> continuous DRAM demand)
//    + free registers (smem caps residency at 4 CTAs/SM, so no tight reg budget).

#define B_ 4
#define C_ 3
#define H_ 720
#define W_ 1280
#define K_ 5
#define R_ 2
#define TPB 128                       // threads per block
#define PIX 256                       // pixels per tile (2 per thread)
#define TPT 8                         // tiles per block
#define TAPS (K_ * K_)
#define TILE_BYTES (TAPS * PIX * 4)   // 25.6 KB per buffer
#define SMEM_TOTAL (2 * TILE_BYTES + 16)

__global__ __launch_bounds__(TPB, 4) void kpn_apply_v9(
    const float* __restrict__ data,
    const float* __restrict__ kern,
    float* __restrict__ out)
{
    extern __shared__ __align__(128) char smem[];
    float*    sk   = (float*)smem;                        // [2][TAPS*PIX]
    uint64_t* mbar = (uint64_t*)(smem + 2 * TILE_BYTES);  // [2]

    const int HW = H_ * W_;
    const int TILES = HW / PIX;                  // 3600 tiles per image
    int tid  = threadIdx.x;
    int base = blockIdx.x * TPT;                 // first tile of this block

    uint32_t mbar_a = (uint32_t)__cvta_generic_to_shared(mbar);
    uint32_t sk_a   = (uint32_t)__cvta_generic_to_shared(sk);

    if (tid == 0) {
        asm volatile("mbarrier.init.shared.b64 [%0], 1;" :: "r"(mbar_a)     : "memory");
        asm volatile("mbarrier.init.shared.b64 [%0], 1;" :: "r"(mbar_a + 8) : "memory");
    }
    __syncthreads();

    // issue 25 bulk copies for tile (base+t) into buffer buf (tid 0 only)
    auto issue = [&](int t, int buf) {
        int tile = base + t;
        int b    = tile / TILES;
        int pos0 = (tile - b * TILES) * PIX;
        const float* kbase = kern + (size_t)b * TAPS * HW + pos0;
        uint32_t mb = mbar_a + buf * 8;
        uint32_t sb = sk_a + buf * TILE_BYTES;
        asm volatile("mbarrier.arrive.expect_tx.shared.b64 _, [%0], %1;"
                     :: "r"(mb), "r"(TILE_BYTES) : "memory");
        #pragma unroll
        for (int tp = 0; tp < TAPS; tp++) {
            asm volatile(
                "cp.async.bulk.shared::cta.global.mbarrier::complete_tx::bytes "
                "[%0], [%1], %2, [%3];"
                :: "r"(sb + tp * PIX * 4),
                   "l"(kbase + (size_t)tp * HW),
                   "r"(PIX * 4),
                   "r"(mb)
                : "memory");
        }
    };

    if (tid == 0) { issue(0, 0); issue(1, 1); }

    for (int t = 0; t < TPT; t++) {
        int buf    = t & 1;
        int parity = (t >> 1) & 1;
        uint32_t mb = mbar_a + buf * 8;

        // wait for this buffer's taps
        {
            uint32_t done;
            asm volatile(
                "{\n\t"
                ".reg .pred p;\n\t"
                "mbarrier.try_wait.parity.acquire.cta.shared::cta.b64 p, [%1], %2;\n\t"
                "selp.b32 %0, 1, 0, p;\n\t"
                "}"
                : "=r"(done) : "r"(mb), "r"((uint32_t)parity) : "memory");
            if (!done) {
                asm volatile(
                    "{\n\t"
                    ".reg .pred P1;\n\t"
                    "WAIT_LOOP_%=:\n\t"
                    "mbarrier.try_wait.parity.acquire.cta.shared::cta.b64 P1, [%0], %1, 0x989680;\n\t"
                    "@P1 bra.uni WAIT_DONE_%=;\n\t"
                    "bra.uni WAIT_LOOP_%=;\n\t"
                    "WAIT_DONE_%=:\n\t"
                    "}"
                    :: "r"(mb), "r"((uint32_t)parity) : "memory");
            }
        }

        // ---- compute tile base+t: 2 adjacent pixels per thread ----
        int tile = base + t;
        int b    = tile / TILES;
        int pos0 = (tile - b * TILES) * PIX;
        int p    = pos0 + 2 * tid;               // first pixel (even)
        int h    = p / W_;
        int w    = p - h * W_;

        const float* skb = sk + buf * (TAPS * PIX);
        const float* dp  = data + (size_t)b * C_ * HW;
        float*       op  = out  + (size_t)b * C_ * HW + p;

        bool interior = (h >= R_) & (h < H_ - R_) & (w >= 2) & (w <= W_ - 4);

        if (interior) {
            float s0 = 0.f, s1 = 0.f;
            float a[C_][2] = {};

            #pragma unroll
            for (int i = 0; i < K_; i++) {
                // 6-float data window per channel: 3 x LDG.64 (8B-aligned, w even)
                const float* drow = dp + (h + i - R_) * W_ + (w - R_);
                float2 v[C_][3];
                #pragma unroll
                for (int c = 0; c < C_; c++) {
                    v[c][0] = *(const float2*)(drow + c * HW);
                    v[c][1] = *(const float2*)(drow + c * HW + 2);
                    v[c][2] = *(const float2*)(drow + c * HW + 4);
                }

                // taps for both pixels: adjacent in smem -> LDS.64
                float e0[K_], e1[K_];
                #pragma unroll
                for (int j = 0; j < K_; j++) {
                    float2 kv = *(const float2*)&skb[(i * K_ + j) * PIX + 2 * tid];
                    e0[j] = __expf(kv.x);        // shift-free softmax (inputs ~N(0,1))
                    e1[j] = __expf(kv.y);
                    s0 += e0[j];
                    s1 += e1[j];
                }

                #pragma unroll
                for (int c = 0; c < C_; c++) {
                    float d0 = v[c][0].x, d1 = v[c][0].y, d2 = v[c][1].x;
                    float d3 = v[c][1].y, d4 = v[c][2].x, d5 = v[c][2].y;
                    a[c][0] += e0[0]*d0 + e0[1]*d1 + e0[2]*d2 + e0[3]*d3 + e0[4]*d4;
                    a[c][1] += e1[0]*d1 + e1[1]*d2 + e1[2]*d3 + e1[3]*d4 + e1[4]*d5;
                }
            }

            float i0 = __frcp_rn(s0), i1 = __frcp_rn(s1);
            #pragma unroll
            for (int c = 0; c < C_; c++) {
                float2 o;
                o.x = a[c][0] * i0;
                o.y = a[c][1] * i1;
                *(float2*)(op + c * HW) = o;
            }
        } else {
            // border: scalar per pixel, taps from smem, zero-pad data
            #pragma unroll
            for (int q = 0; q < 2; q++) {
                int wp = w + q;
                float sum = 0.f, a0 = 0.f, a1 = 0.f, a2 = 0.f;
                #pragma unroll
                for (int i = 0; i < K_; i++) {
                    int yy = h + i - R_;
                    bool yok = (yy >= 0) & (yy < H_);
                    #pragma unroll
                    for (int j = 0; j < K_; j++) {
                        int xx = wp + j - R_;
                        float e = __expf(skb[(i * K_ + j) * PIX + 2 * tid + q]);
                        sum += e;                // denominator includes ALL taps
                        if (yok & (xx >= 0) & (xx < W_)) {
                            const float* d0 = dp + yy * W_ + xx;
                            a0 += e * d0[0];
                            a1 += e * d0[HW];
                            a2 += e * d0[2 * HW];
                        }
                    }
                }
                float inv = __frcp_rn(sum);
                op[q]          = a0 * inv;
                op[HW + q]     = a1 * inv;
                op[2 * HW + q] = a2 * inv;
            }
        }

        // all threads done reading this buffer -> safe to refill
        __syncthreads();
        if (tid == 0 && t + 2 < TPT) issue(t + 2, buf);
    }
}

extern "C" void kernel_launch(void* const* d_in, const int* in_sizes, int n_in,
                              void* d_out, int out_size)
{
    const float* data = (const float*)d_in[0];
    const float* kern = (const float*)d_in[1];
    float* out = (float*)d_out;

    cudaFuncSetAttribute(kpn_apply_v9,
                         cudaFuncAttributeMaxDynamicSharedMemorySize, SMEM_TOTAL);

    const int blocks = B_ * H_ * W_ / PIX / TPT;   // 1800 blocks x 8 tiles
    kpn_apply_v9<<<blocks, TPB, SMEM_TOTAL>>>(data, kern, out);
}

// round 10
// speedup vs baseline: 1.2259x; 1.2259x over previous
#include <cuda_runtime.h>
#include <cuda_bf16.h>
#include <cstdint>

// KernelApply: out[b,c,h,w] = sum_{i,j} softmax(kern[b,:,h,w])[i*5+j] * data_pad[b,c,h+i-2,w+j-2]
// data: [B,C,H,W] f32; kernels: [B,25,H,W] f32; out: [B,C,H,W] f32
//
// v10 = v5 (TMA-staged taps, 1 px/thread, 256t, 8 CTAs/SM) with the tap
// transfer split into 5 per-row chunks on 5 mbarriers: compute row i starts
// when its 5 planes land; later chunks stream under compute. Zero extra smem,
// zero extra registers -> keeps v5's occupancy while shrinking the per-CTA
// serial TMA stall ~5x.

#define B_ 4
#define C_ 3
#define H_ 720
#define W_ 1280
#define K_ 5
#define R_ 2
#define TPB 256
#define TAPS (K_ * K_)

__global__ __launch_bounds__(TPB) void kpn_apply_v10(
    const float* __restrict__ data,
    const float* __restrict__ kern,
    float* __restrict__ out)
{
    __shared__ __align__(128) float sk[TAPS * TPB];      // 25 taps x 256 px = 25.6 KB
    __shared__ __align__(8)   uint64_t mbar[K_];         // one per tap row

    const int HW = H_ * W_;
    const int TILES = HW / TPB;                  // 3600 tiles per image
    int tile = blockIdx.x;
    int b    = tile / TILES;
    int pos0 = (tile - b * TILES) * TPB;         // tile start (256-aligned, single row)
    int tid  = threadIdx.x;

    const float* kbase = kern + (size_t)b * TAPS * HW + pos0;

    uint32_t mbar_a = (uint32_t)__cvta_generic_to_shared(mbar);
    uint32_t sk_a   = (uint32_t)__cvta_generic_to_shared(sk);

    if (tid == 0) {
        #pragma unroll
        for (int i = 0; i < K_; i++)
            asm volatile("mbarrier.init.shared.b64 [%0], 1;"
                         :: "r"(mbar_a + i * 8) : "memory");
    }
    __syncthreads();

    // issue 25 bulk copies, 5 planes per mbarrier (tap row i -> mbar[i])
    if (tid == 0) {
        #pragma unroll
        for (int i = 0; i < K_; i++) {
            uint32_t mb = mbar_a + i * 8;
            asm volatile("mbarrier.arrive.expect_tx.shared.b64 _, [%0], %1;"
                         :: "r"(mb), "r"(K_ * TPB * 4) : "memory");
            #pragma unroll
            for (int j = 0; j < K_; j++) {
                int t = i * K_ + j;
                asm volatile(
                    "cp.async.bulk.shared::cta.global.mbarrier::complete_tx::bytes "
                    "[%0], [%1], %2, [%3];"
                    :: "r"(sk_a + t * TPB * 4),
                       "l"(kbase + (size_t)t * HW),
                       "r"(TPB * 4),
                       "r"(mb)
                    : "memory");
            }
        }
    }

    // ---- compute: 1 pixel per thread, row-pipelined against the TMA stream ----
    int p  = pos0 + tid;
    int h  = p / W_;
    int w  = p - h * W_;

    const float* dp = data + (size_t)b * C_ * HW;
    float*       op = out  + (size_t)b * C_ * HW + p;

    float sum = 0.0f, acc0 = 0.0f, acc1 = 0.0f, acc2 = 0.0f;
    bool interior = (h >= R_) & (h < H_ - R_) & (w >= R_) & (w < W_ - R_);

    #pragma unroll
    for (int i = 0; i < K_; i++) {
        // 1) issue this row's data loads BEFORE waiting on the tap chunk
        float d0[K_], d1[K_], d2[K_];
        if (interior) {
            const float* drow = dp + (h + i - R_) * W_ + (w - R_);
            #pragma unroll
            for (int j = 0; j < K_; j++) d0[j] = drow[j];
            #pragma unroll
            for (int j = 0; j < K_; j++) d1[j] = drow[j + HW];
            #pragma unroll
            for (int j = 0; j < K_; j++) d2[j] = drow[j + 2 * HW];
        }

        // 2) wait for tap row i (phase 0) -- all threads
        {
            uint32_t mb = mbar_a + i * 8;
            uint32_t done;
            asm volatile(
                "{\n\t"
                ".reg .pred p;\n\t"
                "mbarrier.try_wait.parity.acquire.cta.shared::cta.b64 p, [%1], %2;\n\t"
                "selp.b32 %0, 1, 0, p;\n\t"
                "}"
                : "=r"(done) : "r"(mb), "r"(0u) : "memory");
            if (!done) {
                asm volatile(
                    "{\n\t"
                    ".reg .pred P1;\n\t"
                    "WAIT_LOOP_%=:\n\t"
                    "mbarrier.try_wait.parity.acquire.cta.shared::cta.b64 P1, [%0], %1, 0x989680;\n\t"
                    "@P1 bra.uni WAIT_DONE_%=;\n\t"
                    "bra.uni WAIT_LOOP_%=;\n\t"
                    "WAIT_DONE_%=:\n\t"
                    "}"
                    :: "r"(mb), "r"(0u) : "memory");
            }
        }

        // 3) taps from smem, accumulate
        if (interior) {
            #pragma unroll
            for (int j = 0; j < K_; j++) {
                float e = __expf(sk[(i * K_ + j) * TPB + tid]);  // shift-free softmax
                sum  += e;
                acc0 += e * d0[j];
                acc1 += e * d1[j];
                acc2 += e * d2[j];
            }
        } else {
            int yy = h + i - R_;
            bool yok = (yy >= 0) & (yy < H_);
            #pragma unroll
            for (int j = 0; j < K_; j++) {
                int xx = w + j - R_;
                float e = __expf(sk[(i * K_ + j) * TPB + tid]);
                sum += e;                          // denominator includes ALL taps
                if (yok & (xx >= 0) & (xx < W_)) {
                    const float* dq = dp + yy * W_ + xx;
                    acc0 += e * dq[0];
                    acc1 += e * dq[HW];
                    acc2 += e * dq[2 * HW];
                }
            }
        }
    }

    float inv = __frcp_rn(sum);
    op[0]      = acc0 * inv;
    op[HW]     = acc1 * inv;
    op[2 * HW] = acc2 * inv;
}

extern "C" void kernel_launch(void* const* d_in, const int* in_sizes, int n_in,
                              void* d_out, int out_size)
{
    const float* data = (const float*)d_in[0];
    const float* kern = (const float*)d_in[1];
    float* out = (float*)d_out;

    const int blocks = B_ * H_ * W_ / TPB;       // 14400 tiles
    kpn_apply_v10<<<blocks, TPB>>>(data, kern, out);
}